// round 7
// baseline (speedup 1.0000x reference)
#include <cuda_runtime.h>
#include <cuda_bf16.h>
#include <cuda_fp16.h>
#include <cstdint>

#define N_SRC   50000
#define N_DST   50000
#define N_EDGES 800000
#define D       128
#define SCAN_T  1024
#define SCAN_C  49                      // 1024*49 = 50176 >= N_DST
#define CNT_PAD (SCAN_T * SCAN_C)

// ---------------- device-global scratch (allocation-free) ----------------
__device__ __align__(16) __half g_nsrc_h[N_SRC * D];  // fp16 relu(Q h_src + b)
__device__ __align__(16) float  g_nacc[N_DST * D];    // normalized aggregate
__device__ int   g_cnt[CNT_PAD];
__device__ int   g_startv[N_DST];
__device__ int   g_cursor[N_DST];
__device__ int   g_srcs[N_EDGES];
__device__ float g_wsort[N_EDGES];
// Pre-packed weights: bf16 hi/lo pairs, row-major [j][KDIM/2] u32
__device__ __align__(16) uint32_t g_Qhi[128 * 64],  g_Qlo[128 * 64];
__device__ __align__(16) uint32_t g_Whi[128 * 128], g_Wlo[128 * 128];

// ---------------------------------------------------------------------------
// bf16x3 split helpers
// ---------------------------------------------------------------------------
__device__ __forceinline__ void pack2(float x, float y,
                                      uint32_t& hi, uint32_t& lo) {
    __nv_bfloat162 h = __floats2bfloat162_rn(x, y);
    uint32_t hu = reinterpret_cast<uint32_t&>(h);
    float fx = __uint_as_float(hu << 16);
    float fy = __uint_as_float(hu & 0xFFFF0000u);
    __nv_bfloat162 l = __floats2bfloat162_rn(x - fx, y - fy);
    hi = hu;
    lo = reinterpret_cast<uint32_t&>(l);
}

__device__ __forceinline__ void mma_bf16(float* d, const uint32_t* a,
                                         const uint32_t* b) {
    asm volatile(
        "mma.sync.aligned.m16n8k16.row.col.f32.bf16.bf16.f32 "
        "{%0,%1,%2,%3}, {%4,%5,%6,%7}, {%8,%9}, {%0,%1,%2,%3};"
        : "+f"(d[0]), "+f"(d[1]), "+f"(d[2]), "+f"(d[3])
        : "r"(a[0]), "r"(a[1]), "r"(a[2]), "r"(a[3]),
          "r"(b[0]), "r"(b[1]));
}

// ---------------------------------------------------------------------------
// Pre-pack Q_w (128x128) and W_w (128x256) to bf16 hi/lo
// ---------------------------------------------------------------------------
__global__ void prepack_kernel(const float* __restrict__ Qw,
                               const float* __restrict__ Ww) {
    const int nq = 128 * 64, nw = 128 * 128;
    int i = blockIdx.x * blockDim.x + threadIdx.x;
    if (i < nq) {
        float2 v = *(const float2*)(Qw + i * 2);
        pack2(v.x, v.y, g_Qhi[i], g_Qlo[i]);
    } else if (i < nq + nw) {
        int j = i - nq;
        float2 v = *(const float2*)(Ww + j * 2);
        pack2(v.x, v.y, g_Whi[j], g_Wlo[j]);
    }
}

// ---------------------------------------------------------------------------
// CSR build: zero -> histogram -> fused scan (1 block) -> scatter
// ---------------------------------------------------------------------------
__global__ void zero_cnt_kernel() {
    int i = blockIdx.x * blockDim.x + threadIdx.x;
    if (i < CNT_PAD) g_cnt[i] = 0;
}

__global__ void hist_kernel(const int* __restrict__ edst) {
    int e = blockIdx.x * blockDim.x + threadIdx.x;
    if (e < N_EDGES) atomicAdd(&g_cnt[edst[e]], 1);
}

__global__ void scan_fused_kernel() {      // <<<1, 1024>>>
    __shared__ int part[SCAN_T];
    const int t = threadIdx.x;
    const int base = t * SCAN_C;
    int sum = 0;
    for (int i = 0; i < SCAN_C; ++i) sum += g_cnt[base + i];
    part[t] = sum;
    __syncthreads();
    for (int off = 1; off < SCAN_T; off <<= 1) {
        int v = (t >= off) ? part[t - off] : 0;
        __syncthreads();
        part[t] += v;
        __syncthreads();
    }
    int run = part[t] - sum;               // exclusive prefix
    for (int i = 0; i < SCAN_C; ++i) {
        int idx = base + i;
        int c = g_cnt[idx];
        if (idx < N_DST) { g_startv[idx] = run; g_cursor[idx] = run; }
        run += c;
    }
}

__global__ void scatter_kernel(const int* __restrict__ esrc,
                               const int* __restrict__ edst,
                               const float* __restrict__ weights) {
    int e = blockIdx.x * blockDim.x + threadIdx.x;
    if (e >= N_EDGES) return;
    int d   = edst[e];
    int pos = atomicAdd(&g_cursor[d], 1);
    g_srcs[pos]  = esrc[e];
    g_wsort[pos] = weights[e];
}

// ---------------------------------------------------------------------------
// Aggregation: one warp per dst, fp16 gather, fp32 accumulate, one write.
// Writes n/max(ws,1) directly.
// ---------------------------------------------------------------------------
__global__ void aggregate_csr_kernel() {
    const int warp = (blockIdx.x * blockDim.x + threadIdx.x) >> 5;
    const int lane = threadIdx.x & 31;
    if (warp >= N_DST) return;

    const int beg = g_startv[warp];
    const int n   = g_cnt[warp];

    float4 acc = make_float4(0.f, 0.f, 0.f, 0.f);
    float  wsum = 0.f;

    int   s = 0; float w = 0.f;
    if (n > 0) { s = g_srcs[beg]; w = g_wsort[beg]; }
    for (int i = 0; i < n; ++i) {
        int s2 = 0; float w2 = 0.f;
        if (i + 1 < n) { s2 = g_srcs[beg + i + 1]; w2 = g_wsort[beg + i + 1]; }
        uint2 raw = *(const uint2*)(g_nsrc_h + (size_t)s * D + lane * 4);
        float2 p0 = __half22float2(*reinterpret_cast<__half2*>(&raw.x));
        float2 p1 = __half22float2(*reinterpret_cast<__half2*>(&raw.y));
        acc.x = fmaf(p0.x, w, acc.x);
        acc.y = fmaf(p0.y, w, acc.y);
        acc.z = fmaf(p1.x, w, acc.z);
        acc.w = fmaf(p1.y, w, acc.w);
        wsum += w;
        s = s2; w = w2;
    }
    const float inv = 1.0f / fmaxf(wsum, 1.0f);
    float4 o = make_float4(acc.x * inv, acc.y * inv, acc.z * inv, acc.w * inv);
    *(float4*)(g_nacc + (size_t)warp * D + lane * 4) = o;
}

// ---------------------------------------------------------------------------
// Tensor-core GEMM (bf16x3): OUT[i][j] = relu(sum_k A[i][k]*W[j][k] + bias[j])
//   MODE 0: A = h_src (KDIM=128), B = g_Q*, OUT = g_nsrc_h (fp16)
//   MODE 1: A = [g_nacc | h_dst] (KDIM=256), B = g_W*, OUT = d_out (fp32)
// Packed-B arrays are selected INSIDE the kernel by MODE (device-side symbol
// reference — passing __device__ symbols from host was the R6 bug).
// ---------------------------------------------------------------------------
template <int KDIM, int MODE>
__global__ void __launch_bounds__(256, 2)
gemm_bf16x3(const float* __restrict__ A0,
            const float* __restrict__ bias,
            float* __restrict__ out,
            int nrows)
{
    constexpr int P  = 20;                // u32 pitch (16 data + 4 pad)
    constexpr int K2 = KDIM / 2;          // u32 per B row
    const uint32_t* __restrict__ Bhi = (MODE == 0) ? g_Qhi : g_Whi;
    const uint32_t* __restrict__ Blo = (MODE == 0) ? g_Qlo : g_Wlo;

    __shared__ uint32_t As_hi[128 * P];
    __shared__ uint32_t As_lo[128 * P];
    __shared__ uint32_t Bs_hi[128 * P];
    __shared__ uint32_t Bs_lo[128 * P];

    const int tid    = threadIdx.x;
    const int i0     = blockIdx.x * 128;
    const int lane   = tid & 31;
    const int wid    = tid >> 5;
    const int warp_m = wid & 3;
    const int warp_n = wid >> 2;
    const int qr     = lane >> 2;
    const int qc     = lane & 3;

    float acc[2][8][4];
#pragma unroll
    for (int mt = 0; mt < 2; ++mt)
#pragma unroll
        for (int nt = 0; nt < 8; ++nt)
#pragma unroll
            for (int r = 0; r < 4; ++r) acc[mt][nt][r] = 0.f;

    const int  lrow = tid >> 1;           // 0..127
    const int  lkq  = (tid & 1) * 16;     // k offset 0 or 16
    const int  gi   = i0 + lrow;
    const bool ok   = (gi < nrows);

    for (int kc = 0; kc < KDIM; kc += 32) {
        __syncthreads();

#pragma unroll
        for (int q = 0; q < 4; ++q) {
            const int gk = kc + lkq + q * 4;
            const int k2 = (lkq + q * 4) >> 1;      // SMEM u32 col
            // ---- A: load fp32, pack ----
            float4 av = make_float4(0.f, 0.f, 0.f, 0.f);
            if (ok) {
                if (MODE == 0)      av = *(const float4*)(A0 + (size_t)gi * 128 + gk);
                else if (gk < 128)  av = *(const float4*)(g_nacc + (size_t)gi * 128 + gk);
                else                av = *(const float4*)(A0 + (size_t)gi * 128 + (gk - 128));
            }
            uint32_t h0, l0, h1, l1;
            pack2(av.x, av.y, h0, l0);
            pack2(av.z, av.w, h1, l1);
            *(uint2*)(As_hi + lrow * P + k2) = make_uint2(h0, h1);
            *(uint2*)(As_lo + lrow * P + k2) = make_uint2(l0, l1);
            // ---- B: pre-packed, straight copy ----
            const int bidx = lrow * K2 + (gk >> 1);
            *(uint2*)(Bs_hi + lrow * P + k2) = *(const uint2*)(Bhi + bidx);
            *(uint2*)(Bs_lo + lrow * P + k2) = *(const uint2*)(Blo + bidx);
        }
        __syncthreads();

#pragma unroll
        for (int s = 0; s < 2; ++s) {
            const int ks = s * 8;
            uint32_t ahi[2][4], alo[2][4];
#pragma unroll
            for (int mt = 0; mt < 2; ++mt) {
                const int base = (warp_m * 32 + mt * 16 + qr) * P + ks + qc;
                ahi[mt][0] = As_hi[base];
                ahi[mt][1] = As_hi[base + 8 * P];
                ahi[mt][2] = As_hi[base + 4];
                ahi[mt][3] = As_hi[base + 8 * P + 4];
                alo[mt][0] = As_lo[base];
                alo[mt][1] = As_lo[base + 8 * P];
                alo[mt][2] = As_lo[base + 4];
                alo[mt][3] = As_lo[base + 8 * P + 4];
            }
#pragma unroll
            for (int nt = 0; nt < 8; ++nt) {
                const int bb = (warp_n * 64 + nt * 8 + qr) * P + ks + qc;
                uint32_t bh[2] = { Bs_hi[bb], Bs_hi[bb + 4] };
                uint32_t bl[2] = { Bs_lo[bb], Bs_lo[bb + 4] };
#pragma unroll
                for (int mt = 0; mt < 2; ++mt) {
                    mma_bf16(acc[mt][nt], ahi[mt], bh);
                    mma_bf16(acc[mt][nt], alo[mt], bh);
                    mma_bf16(acc[mt][nt], ahi[mt], bl);
                }
            }
        }
    }

    // ---- Epilogue: bias + relu ----
#pragma unroll
    for (int mt = 0; mt < 2; ++mt) {
#pragma unroll
        for (int half = 0; half < 2; ++half) {
            const int row = i0 + warp_m * 32 + mt * 16 + qr + half * 8;
            if (row < nrows) {
#pragma unroll
                for (int nt = 0; nt < 8; ++nt) {
                    const int col = warp_n * 64 + nt * 8 + qc * 2;
                    float vx = fmaxf(acc[mt][nt][half * 2 + 0] + bias[col],     0.f);
                    float vy = fmaxf(acc[mt][nt][half * 2 + 1] + bias[col + 1], 0.f);
                    if (MODE == 0) {
                        *(__half2*)(g_nsrc_h + (size_t)row * 128 + col) =
                            __floats2half2_rn(vx, vy);
                    } else {
                        *(float2*)(out + (size_t)row * 128 + col) =
                            make_float2(vx, vy);
                    }
                }
            }
        }
    }
}

// ---------------------------------------------------------------------------
extern "C" void kernel_launch(void* const* d_in, const int* in_sizes, int n_in,
                              void* d_out, int out_size)
{
    const float* h_src   = (const float*)d_in[0];
    const float* h_dst   = (const float*)d_in[1];
    const float* weights = (const float*)d_in[2];
    const int*   esrc    = (const int*)d_in[3];
    const int*   edst    = (const int*)d_in[4];
    const float* Q_w     = (const float*)d_in[5];
    const float* Q_b     = (const float*)d_in[6];
    const float* W_w     = (const float*)d_in[7];
    const float* W_b     = (const float*)d_in[8];
    float*       out     = (float*)d_out;

    prepack_kernel<<<(128 * 64 + 128 * 128 + 255) / 256, 256>>>(Q_w, W_w);
    zero_cnt_kernel<<<(CNT_PAD + 255) / 256, 256>>>();
    hist_kernel<<<(N_EDGES + 255) / 256, 256>>>(edst);
    scan_fused_kernel<<<1, SCAN_T>>>();
    scatter_kernel<<<(N_EDGES + 255) / 256, 256>>>(esrc, edst, weights);

    gemm_bf16x3<128, 0><<<(N_SRC + 127) / 128, 256>>>(h_src, Q_b, nullptr, N_SRC);
    aggregate_csr_kernel<<<(N_DST * 32 + 255) / 256, 256>>>();
    gemm_bf16x3<256, 1><<<(N_DST + 127) / 128, 256>>>(h_dst, W_b, out, N_DST);
}

// round 8
// speedup vs baseline: 1.5373x; 1.5373x over previous
#include <cuda_runtime.h>
#include <cuda_bf16.h>
#include <cuda_fp16.h>
#include <cstdint>

#define N_SRC   50000
#define N_DST   50000
#define N_EDGES 800000
#define D       128

// ---------------- device-global scratch (allocation-free) ----------------
__device__ __align__(16) __half g_nsrc_h[N_SRC * D];  // fp16 relu(Q h_src + b)
__device__ __align__(16) float  g_nacc[N_DST * D];    // normalized aggregate
__device__ int   g_cnt[N_DST];
__device__ int   g_startv[N_DST];
__device__ int   g_cursor[N_DST];
__device__ int   g_total;
__device__ int   g_srcs[N_EDGES];
__device__ float g_wsort[N_EDGES];
// Pre-packed weights: bf16 hi/lo pairs, row-major [j][KDIM/2] u32
__device__ __align__(16) uint32_t g_Qhi[128 * 64],  g_Qlo[128 * 64];
__device__ __align__(16) uint32_t g_Whi[128 * 128], g_Wlo[128 * 128];

// ---------------------------------------------------------------------------
// bf16x3 split helpers
// ---------------------------------------------------------------------------
__device__ __forceinline__ void pack2(float x, float y,
                                      uint32_t& hi, uint32_t& lo) {
    __nv_bfloat162 h = __floats2bfloat162_rn(x, y);
    uint32_t hu = reinterpret_cast<uint32_t&>(h);
    float fx = __uint_as_float(hu << 16);
    float fy = __uint_as_float(hu & 0xFFFF0000u);
    __nv_bfloat162 l = __floats2bfloat162_rn(x - fx, y - fy);
    hi = hu;
    lo = reinterpret_cast<uint32_t&>(l);
}

__device__ __forceinline__ void mma_bf16(float* d, const uint32_t* a,
                                         const uint32_t* b) {
    asm volatile(
        "mma.sync.aligned.m16n8k16.row.col.f32.bf16.bf16.f32 "
        "{%0,%1,%2,%3}, {%4,%5,%6,%7}, {%8,%9}, {%0,%1,%2,%3};"
        : "+f"(d[0]), "+f"(d[1]), "+f"(d[2]), "+f"(d[3])
        : "r"(a[0]), "r"(a[1]), "r"(a[2]), "r"(a[3]),
          "r"(b[0]), "r"(b[1]));
}

// ---------------------------------------------------------------------------
// Fused prep: zero g_cnt + g_total, pre-pack Q_w / W_w to bf16 hi/lo.
// Grid covers N_DST threads (> 24576 pack elements).
// ---------------------------------------------------------------------------
__global__ void prep_kernel(const float* __restrict__ Qw,
                            const float* __restrict__ Ww) {
    const int nq = 128 * 64, nw = 128 * 128;
    int i = blockIdx.x * blockDim.x + threadIdx.x;
    if (i < N_DST) g_cnt[i] = 0;
    if (i == 0)    g_total = 0;
    if (i < nq) {
        float2 v = *(const float2*)(Qw + i * 2);
        pack2(v.x, v.y, g_Qhi[i], g_Qlo[i]);
    } else if (i < nq + nw) {
        int j = i - nq;
        float2 v = *(const float2*)(Ww + j * 2);
        pack2(v.x, v.y, g_Whi[j], g_Wlo[j]);
    }
}

// ---------------------------------------------------------------------------
// CSR build: histogram -> atomic segment alloc -> scatter
// Segment placement is arbitrary (disjoint is all aggregation needs), so a
// prefix-scan is unnecessary: warp-aggregated atomicAdd allocates bases.
// ---------------------------------------------------------------------------
__global__ void hist_kernel(const int* __restrict__ edst) {
    int e = blockIdx.x * blockDim.x + threadIdx.x;
    if (e < N_EDGES) atomicAdd(&g_cnt[edst[e]], 1);
}

__global__ void alloc_kernel() {
    const int i    = blockIdx.x * blockDim.x + threadIdx.x;
    const int lane = threadIdx.x & 31;
    int c = (i < N_DST) ? g_cnt[i] : 0;
    // warp-inclusive scan of c
    int pfx = c;
#pragma unroll
    for (int o = 1; o < 32; o <<= 1) {
        int v = __shfl_up_sync(0xffffffffu, pfx, o);
        if (lane >= o) pfx += v;
    }
    int wtot = __shfl_sync(0xffffffffu, pfx, 31);
    int wbase = 0;
    if (lane == 31) wbase = atomicAdd(&g_total, wtot);
    wbase = __shfl_sync(0xffffffffu, wbase, 31);
    if (i < N_DST) {
        int base = wbase + pfx - c;
        g_startv[i] = base;
        g_cursor[i] = base;
    }
}

__global__ void scatter_kernel(const int* __restrict__ esrc,
                               const int* __restrict__ edst,
                               const float* __restrict__ weights) {
    int e = blockIdx.x * blockDim.x + threadIdx.x;
    if (e >= N_EDGES) return;
    int d   = edst[e];
    int pos = atomicAdd(&g_cursor[d], 1);
    g_srcs[pos]  = esrc[e];
    g_wsort[pos] = weights[e];
}

// ---------------------------------------------------------------------------
// Aggregation: one warp per dst, fp16 gather (x4 unroll for MLP), fp32
// accumulate, single normalized write.
// ---------------------------------------------------------------------------
__global__ void aggregate_csr_kernel() {
    const int warp = (blockIdx.x * blockDim.x + threadIdx.x) >> 5;
    const int lane = threadIdx.x & 31;
    if (warp >= N_DST) return;

    const int beg = g_startv[warp];
    const int n   = g_cnt[warp];

    float4 acc = make_float4(0.f, 0.f, 0.f, 0.f);
    float  wsum = 0.f;

    int i = 0;
    for (; i + 4 <= n; i += 4) {
        int   s0 = g_srcs[beg + i],     s1 = g_srcs[beg + i + 1];
        int   s2 = g_srcs[beg + i + 2], s3 = g_srcs[beg + i + 3];
        float w0 = g_wsort[beg + i],     w1 = g_wsort[beg + i + 1];
        float w2 = g_wsort[beg + i + 2], w3 = g_wsort[beg + i + 3];
        uint2 r0 = *(const uint2*)(g_nsrc_h + (size_t)s0 * D + lane * 4);
        uint2 r1 = *(const uint2*)(g_nsrc_h + (size_t)s1 * D + lane * 4);
        uint2 r2 = *(const uint2*)(g_nsrc_h + (size_t)s2 * D + lane * 4);
        uint2 r3 = *(const uint2*)(g_nsrc_h + (size_t)s3 * D + lane * 4);
#define ACC_H2(raw, ww) {                                                   \
        float2 p0 = __half22float2(*reinterpret_cast<__half2*>(&(raw).x)); \
        float2 p1 = __half22float2(*reinterpret_cast<__half2*>(&(raw).y)); \
        acc.x = fmaf(p0.x, (ww), acc.x);                                   \
        acc.y = fmaf(p0.y, (ww), acc.y);                                   \
        acc.z = fmaf(p1.x, (ww), acc.z);                                   \
        acc.w = fmaf(p1.y, (ww), acc.w); }
        ACC_H2(r0, w0); ACC_H2(r1, w1); ACC_H2(r2, w2); ACC_H2(r3, w3);
        wsum += (w0 + w1) + (w2 + w3);
    }
    for (; i < n; ++i) {
        int   s = g_srcs[beg + i];
        float w = g_wsort[beg + i];
        uint2 r = *(const uint2*)(g_nsrc_h + (size_t)s * D + lane * 4);
        ACC_H2(r, w);
        wsum += w;
    }
#undef ACC_H2

    const float inv = 1.0f / fmaxf(wsum, 1.0f);
    float4 o = make_float4(acc.x * inv, acc.y * inv, acc.z * inv, acc.w * inv);
    *(float4*)(g_nacc + (size_t)warp * D + lane * 4) = o;
}

// ---------------------------------------------------------------------------
// Tensor-core GEMM (bf16x3): OUT[i][j] = relu(sum_k A[i][k]*W[j][k] + bias[j])
//   MODE 0: A = h_src (KDIM=128), B = g_Q*, OUT = g_nsrc_h (fp16)
//   MODE 1: A = [g_nacc | h_dst] (KDIM=256), B = g_W*, OUT = d_out (fp32)
// ---------------------------------------------------------------------------
template <int KDIM, int MODE>
__global__ void __launch_bounds__(256, 2)
gemm_bf16x3(const float* __restrict__ A0,
            const float* __restrict__ bias,
            float* __restrict__ out,
            int nrows)
{
    constexpr int P  = 20;
    constexpr int K2 = KDIM / 2;
    const uint32_t* __restrict__ Bhi = (MODE == 0) ? g_Qhi : g_Whi;
    const uint32_t* __restrict__ Blo = (MODE == 0) ? g_Qlo : g_Wlo;

    __shared__ uint32_t As_hi[128 * P];
    __shared__ uint32_t As_lo[128 * P];
    __shared__ uint32_t Bs_hi[128 * P];
    __shared__ uint32_t Bs_lo[128 * P];

    const int tid    = threadIdx.x;
    const int i0     = blockIdx.x * 128;
    const int lane   = tid & 31;
    const int wid    = tid >> 5;
    const int warp_m = wid & 3;
    const int warp_n = wid >> 2;
    const int qr     = lane >> 2;
    const int qc     = lane & 3;

    float acc[2][8][4];
#pragma unroll
    for (int mt = 0; mt < 2; ++mt)
#pragma unroll
        for (int nt = 0; nt < 8; ++nt)
#pragma unroll
            for (int r = 0; r < 4; ++r) acc[mt][nt][r] = 0.f;

    const int  lrow = tid >> 1;
    const int  lkq  = (tid & 1) * 16;
    const int  gi   = i0 + lrow;
    const bool ok   = (gi < nrows);

    for (int kc = 0; kc < KDIM; kc += 32) {
        __syncthreads();

#pragma unroll
        for (int q = 0; q < 4; ++q) {
            const int gk = kc + lkq + q * 4;
            const int k2 = (lkq + q * 4) >> 1;
            float4 av = make_float4(0.f, 0.f, 0.f, 0.f);
            if (ok) {
                if (MODE == 0)      av = *(const float4*)(A0 + (size_t)gi * 128 + gk);
                else if (gk < 128)  av = *(const float4*)(g_nacc + (size_t)gi * 128 + gk);
                else                av = *(const float4*)(A0 + (size_t)gi * 128 + (gk - 128));
            }
            uint32_t h0, l0, h1, l1;
            pack2(av.x, av.y, h0, l0);
            pack2(av.z, av.w, h1, l1);
            *(uint2*)(As_hi + lrow * P + k2) = make_uint2(h0, h1);
            *(uint2*)(As_lo + lrow * P + k2) = make_uint2(l0, l1);
            const int bidx = lrow * K2 + (gk >> 1);
            *(uint2*)(Bs_hi + lrow * P + k2) = *(const uint2*)(Bhi + bidx);
            *(uint2*)(Bs_lo + lrow * P + k2) = *(const uint2*)(Blo + bidx);
        }
        __syncthreads();

#pragma unroll
        for (int s = 0; s < 2; ++s) {
            const int ks = s * 8;
            uint32_t ahi[2][4], alo[2][4];
#pragma unroll
            for (int mt = 0; mt < 2; ++mt) {
                const int base = (warp_m * 32 + mt * 16 + qr) * P + ks + qc;
                ahi[mt][0] = As_hi[base];
                ahi[mt][1] = As_hi[base + 8 * P];
                ahi[mt][2] = As_hi[base + 4];
                ahi[mt][3] = As_hi[base + 8 * P + 4];
                alo[mt][0] = As_lo[base];
                alo[mt][1] = As_lo[base + 8 * P];
                alo[mt][2] = As_lo[base + 4];
                alo[mt][3] = As_lo[base + 8 * P + 4];
            }
#pragma unroll
            for (int nt = 0; nt < 8; ++nt) {
                const int bb = (warp_n * 64 + nt * 8 + qr) * P + ks + qc;
                uint32_t bh[2] = { Bs_hi[bb], Bs_hi[bb + 4] };
                uint32_t bl[2] = { Bs_lo[bb], Bs_lo[bb + 4] };
#pragma unroll
                for (int mt = 0; mt < 2; ++mt) {
                    mma_bf16(acc[mt][nt], ahi[mt], bh);
                    mma_bf16(acc[mt][nt], alo[mt], bh);
                    mma_bf16(acc[mt][nt], ahi[mt], bl);
                }
            }
        }
    }

#pragma unroll
    for (int mt = 0; mt < 2; ++mt) {
#pragma unroll
        for (int half = 0; half < 2; ++half) {
            const int row = i0 + warp_m * 32 + mt * 16 + qr + half * 8;
            if (row < nrows) {
#pragma unroll
                for (int nt = 0; nt < 8; ++nt) {
                    const int col = warp_n * 64 + nt * 8 + qc * 2;
                    float vx = fmaxf(acc[mt][nt][half * 2 + 0] + bias[col],     0.f);
                    float vy = fmaxf(acc[mt][nt][half * 2 + 1] + bias[col + 1], 0.f);
                    if (MODE == 0) {
                        *(__half2*)(g_nsrc_h + (size_t)row * 128 + col) =
                            __floats2half2_rn(vx, vy);
                    } else {
                        *(float2*)(out + (size_t)row * 128 + col) =
                            make_float2(vx, vy);
                    }
                }
            }
        }
    }
}

// ---------------------------------------------------------------------------
extern "C" void kernel_launch(void* const* d_in, const int* in_sizes, int n_in,
                              void* d_out, int out_size)
{
    const float* h_src   = (const float*)d_in[0];
    const float* h_dst   = (const float*)d_in[1];
    const float* weights = (const float*)d_in[2];
    const int*   esrc    = (const int*)d_in[3];
    const int*   edst    = (const int*)d_in[4];
    const float* Q_w     = (const float*)d_in[5];
    const float* Q_b     = (const float*)d_in[6];
    const float* W_w     = (const float*)d_in[7];
    const float* W_b     = (const float*)d_in[8];
    float*       out     = (float*)d_out;

    prep_kernel<<<(N_DST + 255) / 256, 256>>>(Q_w, W_w);
    hist_kernel<<<(N_EDGES + 255) / 256, 256>>>(edst);
    alloc_kernel<<<(N_DST + 255) / 256, 256>>>();
    scatter_kernel<<<(N_EDGES + 255) / 256, 256>>>(esrc, edst, weights);

    gemm_bf16x3<128, 0><<<(N_SRC + 127) / 128, 256>>>(h_src, Q_b, nullptr, N_SRC);
    aggregate_csr_kernel<<<(N_DST * 32 + 255) / 256, 256>>>();
    gemm_bf16x3<256, 1><<<(N_DST + 127) / 128, 256>>>(h_dst, W_b, out, N_DST);
}

// round 9
// speedup vs baseline: 1.7018x; 1.1070x over previous
#include <cuda_runtime.h>
#include <cuda_bf16.h>
#include <cuda_fp16.h>
#include <cstdint>

#define N_SRC   50000
#define N_DST   50000
#define N_EDGES 800000
#define D       128

// ---------------- device-global scratch (allocation-free) ----------------
__device__ __align__(16) __half g_nsrc_h[N_SRC * D];  // fp16 relu(Q h_src + b)
__device__ __align__(16) float  g_nacc[N_DST * D];    // normalized aggregate
__device__ int   g_cnt[N_DST];
__device__ int   g_startv[N_DST];
__device__ int   g_cursor[N_DST];
__device__ int   g_total;
__device__ __align__(8) uint2 g_edge[N_EDGES];        // packed (src, weight)
// Pre-packed weights: bf16 hi/lo pairs, row-major [j][KDIM/2] u32
__device__ __align__(16) uint32_t g_Qhi[128 * 64],  g_Qlo[128 * 64];
__device__ __align__(16) uint32_t g_Whi[128 * 128], g_Wlo[128 * 128];

// ---------------------------------------------------------------------------
// bf16x3 split helpers
// ---------------------------------------------------------------------------
__device__ __forceinline__ void pack2(float x, float y,
                                      uint32_t& hi, uint32_t& lo) {
    __nv_bfloat162 h = __floats2bfloat162_rn(x, y);
    uint32_t hu = reinterpret_cast<uint32_t&>(h);
    float fx = __uint_as_float(hu << 16);
    float fy = __uint_as_float(hu & 0xFFFF0000u);
    __nv_bfloat162 l = __floats2bfloat162_rn(x - fx, y - fy);
    hi = hu;
    lo = reinterpret_cast<uint32_t&>(l);
}

__device__ __forceinline__ void mma_bf16(float* d, const uint32_t* a,
                                         const uint32_t* b) {
    asm volatile(
        "mma.sync.aligned.m16n8k16.row.col.f32.bf16.bf16.f32 "
        "{%0,%1,%2,%3}, {%4,%5,%6,%7}, {%8,%9}, {%0,%1,%2,%3};"
        : "+f"(d[0]), "+f"(d[1]), "+f"(d[2]), "+f"(d[3])
        : "r"(a[0]), "r"(a[1]), "r"(a[2]), "r"(a[3]),
          "r"(b[0]), "r"(b[1]));
}

// ---------------------------------------------------------------------------
// Fused prep: zero g_cnt + g_total, pre-pack Q_w / W_w to bf16 hi/lo.
// ---------------------------------------------------------------------------
__global__ void prep_kernel(const float* __restrict__ Qw,
                            const float* __restrict__ Ww) {
    const int nq = 128 * 64, nw = 128 * 128;
    int i = blockIdx.x * blockDim.x + threadIdx.x;
    if (i < N_DST) g_cnt[i] = 0;
    if (i == 0)    g_total = 0;
    if (i < nq) {
        float2 v = *(const float2*)(Qw + i * 2);
        pack2(v.x, v.y, g_Qhi[i], g_Qlo[i]);
    } else if (i < nq + nw) {
        int j = i - nq;
        float2 v = *(const float2*)(Ww + j * 2);
        pack2(v.x, v.y, g_Whi[j], g_Wlo[j]);
    }
}

// ---------------------------------------------------------------------------
// CSR build: histogram -> atomic segment alloc -> scatter (packed 8B stores)
// ---------------------------------------------------------------------------
__global__ void hist_kernel(const int* __restrict__ edst) {
    int e = blockIdx.x * blockDim.x + threadIdx.x;
    if (e < N_EDGES) atomicAdd(&g_cnt[edst[e]], 1);
}

__global__ void alloc_kernel() {
    const int i    = blockIdx.x * blockDim.x + threadIdx.x;
    const int lane = threadIdx.x & 31;
    int c = (i < N_DST) ? g_cnt[i] : 0;
    int pfx = c;
#pragma unroll
    for (int o = 1; o < 32; o <<= 1) {
        int v = __shfl_up_sync(0xffffffffu, pfx, o);
        if (lane >= o) pfx += v;
    }
    int wtot = __shfl_sync(0xffffffffu, pfx, 31);
    int wbase = 0;
    if (lane == 31) wbase = atomicAdd(&g_total, wtot);
    wbase = __shfl_sync(0xffffffffu, wbase, 31);
    if (i < N_DST) {
        int base = wbase + pfx - c;
        g_startv[i] = base;
        g_cursor[i] = base;
    }
}

__global__ void scatter_kernel(const int* __restrict__ esrc,
                               const int* __restrict__ edst,
                               const float* __restrict__ weights) {
    int e = blockIdx.x * blockDim.x + threadIdx.x;
    if (e >= N_EDGES) return;
    int d   = edst[e];
    int pos = atomicAdd(&g_cursor[d], 1);
    g_edge[pos] = make_uint2((uint32_t)esrc[e], __float_as_uint(weights[e]));
}

// ---------------------------------------------------------------------------
// Aggregation: one warp per dst, fp16 gather (x4 unroll), fp32 accumulate,
// single normalized write.
// ---------------------------------------------------------------------------
__global__ void aggregate_csr_kernel() {
    const int warp = (blockIdx.x * blockDim.x + threadIdx.x) >> 5;
    const int lane = threadIdx.x & 31;
    if (warp >= N_DST) return;

    const int beg = g_startv[warp];
    const int n   = g_cnt[warp];

    float4 acc = make_float4(0.f, 0.f, 0.f, 0.f);
    float  wsum = 0.f;

#define ACC_H2(raw, ww) {                                                   \
        float2 p0 = __half22float2(*reinterpret_cast<__half2*>(&(raw).x)); \
        float2 p1 = __half22float2(*reinterpret_cast<__half2*>(&(raw).y)); \
        acc.x = fmaf(p0.x, (ww), acc.x);                                   \
        acc.y = fmaf(p0.y, (ww), acc.y);                                   \
        acc.z = fmaf(p1.x, (ww), acc.z);                                   \
        acc.w = fmaf(p1.y, (ww), acc.w); }

    int i = 0;
    for (; i + 4 <= n; i += 4) {
        uint2 e0 = g_edge[beg + i],     e1 = g_edge[beg + i + 1];
        uint2 e2 = g_edge[beg + i + 2], e3 = g_edge[beg + i + 3];
        uint2 r0 = *(const uint2*)(g_nsrc_h + (size_t)e0.x * D + lane * 4);
        uint2 r1 = *(const uint2*)(g_nsrc_h + (size_t)e1.x * D + lane * 4);
        uint2 r2 = *(const uint2*)(g_nsrc_h + (size_t)e2.x * D + lane * 4);
        uint2 r3 = *(const uint2*)(g_nsrc_h + (size_t)e3.x * D + lane * 4);
        float w0 = __uint_as_float(e0.y), w1 = __uint_as_float(e1.y);
        float w2 = __uint_as_float(e2.y), w3 = __uint_as_float(e3.y);
        ACC_H2(r0, w0); ACC_H2(r1, w1); ACC_H2(r2, w2); ACC_H2(r3, w3);
        wsum += (w0 + w1) + (w2 + w3);
    }
    for (; i < n; ++i) {
        uint2 e = g_edge[beg + i];
        float w = __uint_as_float(e.y);
        uint2 r = *(const uint2*)(g_nsrc_h + (size_t)e.x * D + lane * 4);
        ACC_H2(r, w);
        wsum += w;
    }
#undef ACC_H2

    const float inv = 1.0f / fmaxf(wsum, 1.0f);
    float4 o = make_float4(acc.x * inv, acc.y * inv, acc.z * inv, acc.w * inv);
    *(float4*)(g_nacc + (size_t)warp * D + lane * 4) = o;
}

// ---------------------------------------------------------------------------
// Tensor-core GEMM (bf16x3): OUT[i][j] = relu(sum_k A[i][k]*W[j][k] + bias[j])
//   MODE 0: A = h_src (KDIM=128), B = g_Q*, OUT = g_nsrc_h (fp16)
//   MODE 1: A = [g_nacc | h_dst] (KDIM=256), B = g_W*, OUT = d_out (fp32)
// ---------------------------------------------------------------------------
template <int KDIM, int MODE>
__global__ void __launch_bounds__(256, 2)
gemm_bf16x3(const float* __restrict__ A0,
            const float* __restrict__ bias,
            float* __restrict__ out,
            int nrows)
{
    constexpr int P  = 20;
    constexpr int K2 = KDIM / 2;
    const uint32_t* __restrict__ Bhi = (MODE == 0) ? g_Qhi : g_Whi;
    const uint32_t* __restrict__ Blo = (MODE == 0) ? g_Qlo : g_Wlo;

    __shared__ uint32_t As_hi[128 * P];
    __shared__ uint32_t As_lo[128 * P];
    __shared__ uint32_t Bs_hi[128 * P];
    __shared__ uint32_t Bs_lo[128 * P];

    const int tid    = threadIdx.x;
    const int i0     = blockIdx.x * 128;
    const int lane   = tid & 31;
    const int wid    = tid >> 5;
    const int warp_m = wid & 3;
    const int warp_n = wid >> 2;
    const int qr     = lane >> 2;
    const int qc     = lane & 3;

    float acc[2][8][4];
#pragma unroll
    for (int mt = 0; mt < 2; ++mt)
#pragma unroll
        for (int nt = 0; nt < 8; ++nt)
#pragma unroll
            for (int r = 0; r < 4; ++r) acc[mt][nt][r] = 0.f;

    const int  lrow = tid >> 1;
    const int  lkq  = (tid & 1) * 16;
    const int  gi   = i0 + lrow;
    const bool ok   = (gi < nrows);

    for (int kc = 0; kc < KDIM; kc += 32) {
        __syncthreads();

#pragma unroll
        for (int q = 0; q < 4; ++q) {
            const int gk = kc + lkq + q * 4;
            const int k2 = (lkq + q * 4) >> 1;
            float4 av = make_float4(0.f, 0.f, 0.f, 0.f);
            if (ok) {
                if (MODE == 0)      av = *(const float4*)(A0 + (size_t)gi * 128 + gk);
                else if (gk < 128)  av = *(const float4*)(g_nacc + (size_t)gi * 128 + gk);
                else                av = *(const float4*)(A0 + (size_t)gi * 128 + (gk - 128));
            }
            uint32_t h0, l0, h1, l1;
            pack2(av.x, av.y, h0, l0);
            pack2(av.z, av.w, h1, l1);
            *(uint2*)(As_hi + lrow * P + k2) = make_uint2(h0, h1);
            *(uint2*)(As_lo + lrow * P + k2) = make_uint2(l0, l1);
            const int bidx = lrow * K2 + (gk >> 1);
            *(uint2*)(Bs_hi + lrow * P + k2) = *(const uint2*)(Bhi + bidx);
            *(uint2*)(Bs_lo + lrow * P + k2) = *(const uint2*)(Blo + bidx);
        }
        __syncthreads();

#pragma unroll
        for (int s = 0; s < 2; ++s) {
            const int ks = s * 8;
            uint32_t ahi[2][4], alo[2][4];
#pragma unroll
            for (int mt = 0; mt < 2; ++mt) {
                const int base = (warp_m * 32 + mt * 16 + qr) * P + ks + qc;
                ahi[mt][0] = As_hi[base];
                ahi[mt][1] = As_hi[base + 8 * P];
                ahi[mt][2] = As_hi[base + 4];
                ahi[mt][3] = As_hi[base + 8 * P + 4];
                alo[mt][0] = As_lo[base];
                alo[mt][1] = As_lo[base + 8 * P];
                alo[mt][2] = As_lo[base + 4];
                alo[mt][3] = As_lo[base + 8 * P + 4];
            }
#pragma unroll
            for (int nt = 0; nt < 8; ++nt) {
                const int bb = (warp_n * 64 + nt * 8 + qr) * P + ks + qc;
                uint32_t bh[2] = { Bs_hi[bb], Bs_hi[bb + 4] };
                uint32_t bl[2] = { Bs_lo[bb], Bs_lo[bb + 4] };
#pragma unroll
                for (int mt = 0; mt < 2; ++mt) {
                    mma_bf16(acc[mt][nt], ahi[mt], bh);
                    mma_bf16(acc[mt][nt], alo[mt], bh);
                    mma_bf16(acc[mt][nt], ahi[mt], bl);
                }
            }
        }
    }

#pragma unroll
    for (int mt = 0; mt < 2; ++mt) {
#pragma unroll
        for (int half = 0; half < 2; ++half) {
            const int row = i0 + warp_m * 32 + mt * 16 + qr + half * 8;
            if (row < nrows) {
#pragma unroll
                for (int nt = 0; nt < 8; ++nt) {
                    const int col = warp_n * 64 + nt * 8 + qc * 2;
                    float vx = fmaxf(acc[mt][nt][half * 2 + 0] + bias[col],     0.f);
                    float vy = fmaxf(acc[mt][nt][half * 2 + 1] + bias[col + 1], 0.f);
                    if (MODE == 0) {
                        *(__half2*)(g_nsrc_h + (size_t)row * 128 + col) =
                            __floats2half2_rn(vx, vy);
                    } else {
                        *(float2*)(out + (size_t)row * 128 + col) =
                            make_float2(vx, vy);
                    }
                }
            }
        }
    }
}

// ---------------------------------------------------------------------------
// Launch: fork CSR chain onto a side stream so it overlaps GEMM0.
//   main: prep -> gemm0 ------------------\
//   side:      \-> hist -> alloc -> scatter -> (join) aggregate -> gemm1
// ---------------------------------------------------------------------------
extern "C" void kernel_launch(void* const* d_in, const int* in_sizes, int n_in,
                              void* d_out, int out_size)
{
    const float* h_src   = (const float*)d_in[0];
    const float* h_dst   = (const float*)d_in[1];
    const float* weights = (const float*)d_in[2];
    const int*   esrc    = (const int*)d_in[3];
    const int*   edst    = (const int*)d_in[4];
    const float* Q_w     = (const float*)d_in[5];
    const float* Q_b     = (const float*)d_in[6];
    const float* W_w     = (const float*)d_in[7];
    const float* W_b     = (const float*)d_in[8];
    float*       out     = (float*)d_out;

    static cudaStream_t s2 = nullptr;
    static cudaEvent_t  evFork = nullptr, evJoin = nullptr;
    if (!s2) {
        cudaStreamCreateWithFlags(&s2, cudaStreamNonBlocking);
        cudaEventCreateWithFlags(&evFork, cudaEventDisableTiming);
        cudaEventCreateWithFlags(&evJoin, cudaEventDisableTiming);
    }

    prep_kernel<<<(N_DST + 255) / 256, 256>>>(Q_w, W_w);

    cudaEventRecord(evFork, 0);
    cudaStreamWaitEvent(s2, evFork, 0);

    // side stream: CSR build
    hist_kernel<<<(N_EDGES + 255) / 256, 256, 0, s2>>>(edst);
    alloc_kernel<<<(N_DST + 255) / 256, 256, 0, s2>>>();
    scatter_kernel<<<(N_EDGES + 255) / 256, 256, 0, s2>>>(esrc, edst, weights);
    cudaEventRecord(evJoin, s2);

    // main stream: GEMM0 (overlaps CSR build)
    gemm_bf16x3<128, 0><<<(N_SRC + 127) / 128, 256>>>(h_src, Q_b, nullptr, N_SRC);

    cudaStreamWaitEvent(0, evJoin, 0);
    aggregate_csr_kernel<<<(N_DST * 32 + 255) / 256, 256>>>();
    gemm_bf16x3<256, 1><<<(N_DST + 127) / 128, 256>>>(h_dst, W_b, out, N_DST);
}